// round 14
// baseline (speedup 1.0000x reference)
#include <cuda_runtime.h>
#include <cuda_fp16.h>
#include <cstdint>

#define BATCH 32
#define LQ    2048
#define SK    2048
#define EDIM  64
#define DDIM  64

#define BM 128
#define BN 32
#define NT 128
#define NTILES (SK / BN)

#define QSCALE 0.18033688011112042f   // (1/sqrt(64)) * log2(e)

// ---- shared memory (bytes) ----
#define SM_KH  0          // double buf fp16 K[key][e] 32x64 -> 4096 B each
#define SM_VH  8192       // double buf fp16 V[key][d] 32x64 -> 4096 B each
#define SM_TOTAL 16384

__device__ __forceinline__ uint32_t smem_u32(const void* p) {
    uint32_t a;
    asm("{ .reg .u64 t; cvta.to.shared.u64 t, %1; cvt.u32.u64 %0, t; }" : "=r"(a) : "l"(p));
    return a;
}
__device__ __forceinline__ float ex2(float x) {
    float r;
    asm("ex2.approx.ftz.f32 %0, %1;" : "=f"(r) : "f"(x));
    return r;
}
__device__ __forceinline__ uint32_t pack_h2(float lo, float hi) {
    __half2 h = __floats2half2_rn(lo, hi);
    return *reinterpret_cast<uint32_t*>(&h);
}
__device__ __forceinline__ void mma16(float c[4], const uint32_t a[4],
                                      uint32_t b0, uint32_t b1) {
    asm volatile(
        "mma.sync.aligned.m16n8k16.row.col.f32.f16.f16.f32 "
        "{%0,%1,%2,%3}, {%4,%5,%6,%7}, {%8,%9}, {%0,%1,%2,%3};"
        : "+f"(c[0]), "+f"(c[1]), "+f"(c[2]), "+f"(c[3])
        : "r"(a[0]), "r"(a[1]), "r"(a[2]), "r"(a[3]), "r"(b0), "r"(b1));
}
__device__ __forceinline__ void ldsm4(uint32_t r[4], uint32_t addr) {
    asm volatile("ldmatrix.sync.aligned.m8n8.x4.shared.b16 {%0,%1,%2,%3}, [%4];"
        : "=r"(r[0]), "=r"(r[1]), "=r"(r[2]), "=r"(r[3]) : "r"(addr));
}
__device__ __forceinline__ void ldsm4t(uint32_t r[4], uint32_t addr) {
    asm volatile("ldmatrix.sync.aligned.m8n8.x4.trans.shared.b16 {%0,%1,%2,%3}, [%4];"
        : "=r"(r[0]), "=r"(r[1]), "=r"(r[2]), "=r"(r[3]) : "r"(addr));
}

// store a quarter of a 64-float row as 2 swizzled 16B fp16 chunks
__device__ __forceinline__ void store_tile_h(char* base, int row, int q,
                                             const float4 p[4]) {
    uint4 c0 = make_uint4(pack_h2(p[0].x, p[0].y), pack_h2(p[0].z, p[0].w),
                          pack_h2(p[1].x, p[1].y), pack_h2(p[1].z, p[1].w));
    uint4 c1 = make_uint4(pack_h2(p[2].x, p[2].y), pack_h2(p[2].z, p[2].w),
                          pack_h2(p[3].x, p[3].y), pack_h2(p[3].z, p[3].w));
    int r7 = row & 7;
    *reinterpret_cast<uint4*>(base + row * 128 + (((2 * q)     ^ r7) << 4)) = c0;
    *reinterpret_cast<uint4*>(base + row * 128 + (((2 * q + 1) ^ r7) << 4)) = c1;
}

__global__ __launch_bounds__(NT, 2)
void fa8(const float* __restrict__ Q, const float* __restrict__ K,
         const float* __restrict__ V, float* __restrict__ O)
{
    extern __shared__ char smem[];
    const uint32_t sb = smem_u32(smem);

    const int tid  = threadIdx.x;
    const int lane = tid & 31;
    const int warp = tid >> 5;
    const int g    = lane >> 2;
    const int t4   = lane & 3;
    const int r0   = warp << 5;            // 32 query rows per warp

    const int b    = blockIdx.y;
    const int qblk = blockIdx.x;
    const float* Qb = Q + ((size_t)b * LQ + (size_t)qblk * BM) * EDIM;
    const float4* K4 = reinterpret_cast<const float4*>(K + (size_t)b * SK * EDIM);
    const float4* V4 = reinterpret_cast<const float4*>(V + (size_t)b * SK * DDIM);

    // loader indexing: 4 threads per 64-float row, rows 0..31
    const int lrow = tid >> 2;
    const int lq   = tid & 3;

    // ldmatrix lane-constant address parts (layouts verified R9/R13)
    const int l7 = lane & 7;
    const int lm = lane >> 3;
    const uint32_t kla = (uint32_t)(l7 * 128 + ((lm ^ l7) << 4));
    const uint32_t vla = (uint32_t)(((lm & 1) * 8 + l7) * 128 + ((((lm >> 1) ^ l7)) << 4));

    // ---- prologue: tile 0 -> buf 0 ----
    {
        float4 tp[4];
        #pragma unroll
        for (int i = 0; i < 4; i++) tp[i] = K4[lrow * 16 + lq * 4 + i];
        store_tile_h(smem + SM_KH, lrow, lq, tp);
        #pragma unroll
        for (int i = 0; i < 4; i++) tp[i] = V4[lrow * 16 + lq * 4 + i];
        store_tile_h(smem + SM_VH, lrow, lq, tp);
    }

    // ---- Q -> fp16 A-fragments in 32 persistent registers ----
    uint32_t aq[2][4][4];
    #pragma unroll
    for (int rb = 0; rb < 2; rb++) {
        const float* q0 = Qb + (size_t)(r0 + 16 * rb + g) * EDIM;
        const float* q1 = q0 + 8 * EDIM;
        #pragma unroll
        for (int kk = 0; kk < 4; kk++) {
            int c = 16 * kk + 2 * t4;
            aq[rb][kk][0] = pack_h2(q0[c    ] * QSCALE, q0[c + 1] * QSCALE);
            aq[rb][kk][1] = pack_h2(q1[c    ] * QSCALE, q1[c + 1] * QSCALE);
            aq[rb][kk][2] = pack_h2(q0[c + 8] * QSCALE, q0[c + 9] * QSCALE);
            aq[rb][kk][3] = pack_h2(q1[c + 8] * QSCALE, q1[c + 9] * QSCALE);
        }
    }
    __syncthreads();

    float o[2][8][4];
    #pragma unroll
    for (int rb = 0; rb < 2; rb++)
        #pragma unroll
        for (int nb = 0; nb < 8; nb++)
            #pragma unroll
            for (int i = 0; i < 4; i++) o[rb][nb][i] = 0.0f;
    float lsum[2][2] = {{0.0f, 0.0f}, {0.0f, 0.0f}};

    for (int tt = 0; tt < NTILES; tt++) {
        const uint32_t kb = sb + SM_KH + (uint32_t)((tt & 1) * 4096) + kla;
        const uint32_t vb = sb + SM_VH + (uint32_t)((tt & 1) * 4096) + vla;

        // ---- K prefetch LDG for tile tt+1 ----
        float4 kp[4];
        if (tt + 1 < NTILES) {
            const float4* Ks = K4 + (size_t)(tt + 1) * BN * (EDIM / 4);
            #pragma unroll
            for (int i = 0; i < 4; i++) kp[i] = Ks[lrow * 16 + lq * 4 + i];
        }
        float4 vp[4];

        // ---- interleaved: per nb-pair j do MMA1 -> softmax -> MMA2 ----
        #pragma unroll
        for (int j = 0; j < 2; j++) {
            const int nb0 = 2 * j;
            // K fragments for both nb of this pair
            uint32_t w0a[4], w0b[4], w1a[4], w1b[4];
            uint32_t ka0 = kb + (uint32_t)(nb0 * 1024);
            uint32_t ka1 = kb + (uint32_t)((nb0 + 1) * 1024);
            ldsm4(w0a, ka0);          // nb0: e-chunks 0..3
            ldsm4(w0b, ka0 ^ 64u);    // nb0: e-chunks 4..7
            ldsm4(w1a, ka1);          // nb1
            ldsm4(w1b, ka1 ^ 64u);

            // MMA1 + softmax, split accumulator chains (depth 2 + add)
            uint32_t ph[2][2][2];     // [rb][nb-in-pair][half]
            #pragma unroll
            for (int rb = 0; rb < 2; rb++) {
                float sL[4] = {0, 0, 0, 0}, sH[4] = {0, 0, 0, 0};
                mma16(sL, aq[rb][0], w0a[0], w0a[1]);
                mma16(sL, aq[rb][1], w0a[2], w0a[3]);
                mma16(sH, aq[rb][2], w0b[0], w0b[1]);
                mma16(sH, aq[rb][3], w0b[2], w0b[3]);
                float p0 = ex2(sL[0] + sH[0]);
                float p1 = ex2(sL[1] + sH[1]);
                float p2 = ex2(sL[2] + sH[2]);
                float p3 = ex2(sL[3] + sH[3]);
                lsum[rb][0] += p0 + p1;
                lsum[rb][1] += p2 + p3;
                ph[rb][0][0] = pack_h2(p0, p1);
                ph[rb][0][1] = pack_h2(p2, p3);

                float tL[4] = {0, 0, 0, 0}, tH[4] = {0, 0, 0, 0};
                mma16(tL, aq[rb][0], w1a[0], w1a[1]);
                mma16(tL, aq[rb][1], w1a[2], w1a[3]);
                mma16(tH, aq[rb][2], w1b[0], w1b[1]);
                mma16(tH, aq[rb][3], w1b[2], w1b[3]);
                float q0 = ex2(tL[0] + tH[0]);
                float q1 = ex2(tL[1] + tH[1]);
                float q2 = ex2(tL[2] + tH[2]);
                float q3 = ex2(tL[3] + tH[3]);
                lsum[rb][0] += q0 + q1;
                lsum[rb][1] += q2 + q3;
                ph[rb][1][0] = pack_h2(q0, q1);
                ph[rb][1][1] = pack_h2(q2, q3);
            }

            // MMA2 for key-slice ks=j (keys 16j..16j+15)
            uint32_t a0[4] = {ph[0][0][0], ph[0][0][1], ph[0][1][0], ph[0][1][1]};
            uint32_t a1[4] = {ph[1][0][0], ph[1][0][1], ph[1][1][0], ph[1][1][1]};
            uint32_t vk = vb + (uint32_t)(j * 2048);
            #pragma unroll
            for (int nbp = 0; nbp < 4; nbp++) {
                uint32_t w[4];
                ldsm4t(w, vk ^ (uint32_t)(nbp << 5));
                mma16(o[0][2 * nbp    ], a0, w[0], w[1]);
                mma16(o[0][2 * nbp + 1], a0, w[2], w[3]);
                mma16(o[1][2 * nbp    ], a1, w[0], w[1]);
                mma16(o[1][2 * nbp + 1], a1, w[2], w[3]);
            }

            // between the two pairs: store K(t+1), launch V(t+1) LDG
            if (j == 0 && tt + 1 < NTILES) {
                store_tile_h(smem + SM_KH + ((tt + 1) & 1) * 4096, lrow, lq, kp);
                const float4* Vs = V4 + (size_t)(tt + 1) * BN * (DDIM / 4);
                #pragma unroll
                for (int i = 0; i < 4; i++) vp[i] = Vs[lrow * 16 + lq * 4 + i];
            }
        }

        // ---- store V(t+1) ----
        if (tt + 1 < NTILES) {
            store_tile_h(smem + SM_VH + ((tt + 1) & 1) * 4096, lrow, lq, vp);
        }
        __syncthreads();
    }

    // ---- row-sum reduction across each quad ----
    #pragma unroll
    for (int rb = 0; rb < 2; rb++) {
        #pragma unroll
        for (int h = 0; h < 2; h++) {
            lsum[rb][h] += __shfl_xor_sync(0xffffffffu, lsum[rb][h], 1);
            lsum[rb][h] += __shfl_xor_sync(0xffffffffu, lsum[rb][h], 2);
        }
    }

    // ---- epilogue: normalize, store ----
    float* Ob = O + ((size_t)b * LQ + (size_t)qblk * BM) * DDIM;
    #pragma unroll
    for (int rb = 0; rb < 2; rb++) {
        const float i0 = 1.0f / lsum[rb][0];
        const float i1 = 1.0f / lsum[rb][1];
        #pragma unroll
        for (int nb = 0; nb < 8; nb++) {
            int row = r0 + 16 * rb + g;
            int col = 8 * nb + 2 * t4;
            *reinterpret_cast<float2*>(&Ob[(size_t)row * DDIM + col]) =
                make_float2(o[rb][nb][0] * i0, o[rb][nb][1] * i0);
            *reinterpret_cast<float2*>(&Ob[(size_t)(row + 8) * DDIM + col]) =
                make_float2(o[rb][nb][2] * i1, o[rb][nb][3] * i1);
        }
    }
}

extern "C" void kernel_launch(void* const* d_in, const int* in_sizes, int n_in,
                              void* d_out, int out_size)
{
    const float* Q = (const float*)d_in[0];
    const float* K = (const float*)d_in[1];
    const float* V = (const float*)d_in[2];
    float* O = (float*)d_out;

    cudaFuncSetAttribute(fa8, cudaFuncAttributeMaxDynamicSharedMemorySize, SM_TOTAL);
    dim3 grid(LQ / BM, BATCH);
    fa8<<<grid, NT, SM_TOTAL>>>(Q, K, V, O);
}

// round 15
// speedup vs baseline: 1.0109x; 1.0109x over previous
#include <cuda_runtime.h>
#include <cuda_fp16.h>
#include <cstdint>

#define BATCH 32
#define LQ    2048
#define SK    2048
#define EDIM  64
#define DDIM  64

#define BM 128
#define BN 32
#define NT 128
#define NTILES (SK / BN)

#define QSCALE 0.18033688011112042f   // (1/sqrt(64)) * log2(e)
#define ONES_H2 0x3C003C00u           // half2(1.0, 1.0)

// ---- shared memory (bytes) ----
#define SM_KH  0          // double buf fp16 K[key][e] 32x64 -> 4096 B each
#define SM_VH  8192       // double buf fp16 V[key][d] 32x64 -> 4096 B each
#define SM_TOTAL 16384

__device__ __forceinline__ uint32_t smem_u32(const void* p) {
    uint32_t a;
    asm("{ .reg .u64 t; cvta.to.shared.u64 t, %1; cvt.u32.u64 %0, t; }" : "=r"(a) : "l"(p));
    return a;
}
__device__ __forceinline__ float ex2(float x) {
    float r;
    asm("ex2.approx.ftz.f32 %0, %1;" : "=f"(r) : "f"(x));
    return r;
}
__device__ __forceinline__ uint32_t pack_h2(float lo, float hi) {
    __half2 h = __floats2half2_rn(lo, hi);
    return *reinterpret_cast<uint32_t*>(&h);
}
__device__ __forceinline__ void mma16(float c[4], const uint32_t a[4],
                                      uint32_t b0, uint32_t b1) {
    asm volatile(
        "mma.sync.aligned.m16n8k16.row.col.f32.f16.f16.f32 "
        "{%0,%1,%2,%3}, {%4,%5,%6,%7}, {%8,%9}, {%0,%1,%2,%3};"
        : "+f"(c[0]), "+f"(c[1]), "+f"(c[2]), "+f"(c[3])
        : "r"(a[0]), "r"(a[1]), "r"(a[2]), "r"(a[3]), "r"(b0), "r"(b1));
}
__device__ __forceinline__ void ldsm4(uint32_t r[4], uint32_t addr) {
    asm volatile("ldmatrix.sync.aligned.m8n8.x4.shared.b16 {%0,%1,%2,%3}, [%4];"
        : "=r"(r[0]), "=r"(r[1]), "=r"(r[2]), "=r"(r[3]) : "r"(addr));
}
__device__ __forceinline__ void ldsm4t(uint32_t r[4], uint32_t addr) {
    asm volatile("ldmatrix.sync.aligned.m8n8.x4.trans.shared.b16 {%0,%1,%2,%3}, [%4];"
        : "=r"(r[0]), "=r"(r[1]), "=r"(r[2]), "=r"(r[3]) : "r"(addr));
}

// store a quarter of a 64-float row as 2 swizzled 16B fp16 chunks
__device__ __forceinline__ void store_tile_h(char* base, int row, int q,
                                             const float4 p[4]) {
    uint4 c0 = make_uint4(pack_h2(p[0].x, p[0].y), pack_h2(p[0].z, p[0].w),
                          pack_h2(p[1].x, p[1].y), pack_h2(p[1].z, p[1].w));
    uint4 c1 = make_uint4(pack_h2(p[2].x, p[2].y), pack_h2(p[2].z, p[2].w),
                          pack_h2(p[3].x, p[3].y), pack_h2(p[3].z, p[3].w));
    int r7 = row & 7;
    *reinterpret_cast<uint4*>(base + row * 128 + (((2 * q)     ^ r7) << 4)) = c0;
    *reinterpret_cast<uint4*>(base + row * 128 + (((2 * q + 1) ^ r7) << 4)) = c1;
}

// K fragments for one nb (8 regs: e-chunks 0..3 and 4..7)
__device__ __forceinline__ void ld_kfrags(uint32_t w[8], uint32_t kb, int nb) {
    uint32_t a = kb + (uint32_t)(nb * 1024);
    ldsm4(w,     a);
    ldsm4(w + 4, a ^ 64u);
}
// V fragments for one ks (16 regs: 4 nbp groups)
__device__ __forceinline__ void ld_vfrags(uint32_t v[16], uint32_t vb, int ks) {
    uint32_t a = vb + (uint32_t)(ks * 2048);
    ldsm4t(v,      a);
    ldsm4t(v + 4,  a ^ 32u);
    ldsm4t(v + 8,  a ^ 64u);
    ldsm4t(v + 12, a ^ 96u);
}

__global__ __launch_bounds__(NT, 2)
void fa9(const float* __restrict__ Q, const float* __restrict__ K,
         const float* __restrict__ V, float* __restrict__ O)
{
    extern __shared__ char smem[];
    const uint32_t sb = smem_u32(smem);

    const int tid  = threadIdx.x;
    const int lane = tid & 31;
    const int warp = tid >> 5;
    const int g    = lane >> 2;
    const int t4   = lane & 3;
    const int r0   = warp << 5;            // 32 query rows per warp

    const int b    = blockIdx.y;
    const int qblk = blockIdx.x;
    const float* Qb = Q + ((size_t)b * LQ + (size_t)qblk * BM) * EDIM;
    const float4* K4 = reinterpret_cast<const float4*>(K + (size_t)b * SK * EDIM);
    const float4* V4 = reinterpret_cast<const float4*>(V + (size_t)b * SK * DDIM);

    // loader indexing: 4 threads per 64-float row, rows 0..31
    const int lrow = tid >> 2;
    const int lq   = tid & 3;

    // ldmatrix lane-constant address parts (layouts verified R9/R13)
    const int l7 = lane & 7;
    const int lm = lane >> 3;
    const uint32_t kla = (uint32_t)(l7 * 128 + ((lm ^ l7) << 4));
    const uint32_t vla = (uint32_t)(((lm & 1) * 8 + l7) * 128 + ((((lm >> 1) ^ l7)) << 4));

    // ---- prologue: tile 0 -> buf 0 ----
    {
        float4 tp[4];
        #pragma unroll
        for (int i = 0; i < 4; i++) tp[i] = K4[lrow * 16 + lq * 4 + i];
        store_tile_h(smem + SM_KH, lrow, lq, tp);
        #pragma unroll
        for (int i = 0; i < 4; i++) tp[i] = V4[lrow * 16 + lq * 4 + i];
        store_tile_h(smem + SM_VH, lrow, lq, tp);
    }

    // ---- Q -> fp16 A-fragments in 32 persistent registers ----
    uint32_t aq[2][4][4];
    #pragma unroll
    for (int rb = 0; rb < 2; rb++) {
        const float* q0 = Qb + (size_t)(r0 + 16 * rb + g) * EDIM;
        const float* q1 = q0 + 8 * EDIM;
        #pragma unroll
        for (int kk = 0; kk < 4; kk++) {
            int c = 16 * kk + 2 * t4;
            aq[rb][kk][0] = pack_h2(q0[c    ] * QSCALE, q0[c + 1] * QSCALE);
            aq[rb][kk][1] = pack_h2(q1[c    ] * QSCALE, q1[c + 1] * QSCALE);
            aq[rb][kk][2] = pack_h2(q0[c + 8] * QSCALE, q0[c + 9] * QSCALE);
            aq[rb][kk][3] = pack_h2(q1[c + 8] * QSCALE, q1[c + 9] * QSCALE);
        }
    }
    __syncthreads();

    float o[2][8][4];
    #pragma unroll
    for (int rb = 0; rb < 2; rb++)
        #pragma unroll
        for (int nb = 0; nb < 8; nb++)
            #pragma unroll
            for (int i = 0; i < 4; i++) o[rb][nb][i] = 0.0f;
    float o1[2][4];                        // ones-column row sums (cols all equal)
    #pragma unroll
    for (int rb = 0; rb < 2; rb++)
        #pragma unroll
        for (int i = 0; i < 4; i++) o1[rb][i] = 0.0f;

    for (int tt = 0; tt < NTILES; tt++) {
        const uint32_t kb = sb + SM_KH + (uint32_t)((tt & 1) * 4096) + kla;
        const uint32_t vb = sb + SM_VH + (uint32_t)((tt & 1) * 4096) + vla;

        // ---- K prefetch LDG for tile tt+1 ----
        float4 kp[4];
        if (tt + 1 < NTILES) {
            const float4* Ks = K4 + (size_t)(tt + 1) * BN * (EDIM / 4);
            #pragma unroll
            for (int i = 0; i < 4; i++) kp[i] = Ks[lrow * 16 + lq * 4 + i];
        }

        // ---- MMA1 fused with softmax, software-pipelined K LDSM ----
        uint32_t ph[2][4][2];
        uint32_t wf[2][8];
        ld_kfrags(wf[0], kb, 0);
        #pragma unroll
        for (int nb = 0; nb < 4; nb++) {
            const uint32_t* w = wf[nb & 1];
            if (nb < 3) ld_kfrags(wf[(nb + 1) & 1], kb, nb + 1);
            #pragma unroll
            for (int rb = 0; rb < 2; rb++) {
                float sL[4] = {0, 0, 0, 0}, sH[4] = {0, 0, 0, 0};
                mma16(sL, aq[rb][0], w[0], w[1]);
                mma16(sL, aq[rb][1], w[2], w[3]);
                mma16(sH, aq[rb][2], w[4], w[5]);
                mma16(sH, aq[rb][3], w[6], w[7]);
                float p0 = ex2(sL[0] + sH[0]);
                float p1 = ex2(sL[1] + sH[1]);
                float p2 = ex2(sL[2] + sH[2]);
                float p3 = ex2(sL[3] + sH[3]);
                ph[rb][nb][0] = pack_h2(p0, p1);
                ph[rb][nb][1] = pack_h2(p2, p3);
            }
        }

        // ---- store K(t+1); V prefetch LDG ----
        float4 vp[4];
        if (tt + 1 < NTILES) {
            store_tile_h(smem + SM_KH + ((tt + 1) & 1) * 4096, lrow, lq, kp);
            const float4* Vs = V4 + (size_t)(tt + 1) * BN * (DDIM / 4);
            #pragma unroll
            for (int i = 0; i < 4; i++) vp[i] = Vs[lrow * 16 + lq * 4 + i];
        }

        // ---- MMA2: O += P V, software-pipelined V LDSM; ones-MMA row sums ----
        uint32_t vf[2][16];
        ld_vfrags(vf[0], vb, 0);
        #pragma unroll
        for (int ks = 0; ks < 2; ks++) {
            const uint32_t* v = vf[ks & 1];
            if (ks == 0) ld_vfrags(vf[1], vb, 1);
            uint32_t a0[4] = {ph[0][2 * ks][0], ph[0][2 * ks][1],
                              ph[0][2 * ks + 1][0], ph[0][2 * ks + 1][1]};
            uint32_t a1[4] = {ph[1][2 * ks][0], ph[1][2 * ks][1],
                              ph[1][2 * ks + 1][0], ph[1][2 * ks + 1][1]};
            #pragma unroll
            for (int nbp = 0; nbp < 4; nbp++) {
                mma16(o[0][2 * nbp    ], a0, v[4 * nbp + 0], v[4 * nbp + 1]);
                mma16(o[0][2 * nbp + 1], a0, v[4 * nbp + 2], v[4 * nbp + 3]);
                mma16(o[1][2 * nbp    ], a1, v[4 * nbp + 0], v[4 * nbp + 1]);
                mma16(o[1][2 * nbp + 1], a1, v[4 * nbp + 2], v[4 * nbp + 3]);
            }
            mma16(o1[0], a0, ONES_H2, ONES_H2);   // row sums, B = ones
            mma16(o1[1], a1, ONES_H2, ONES_H2);
        }

        // ---- store V(t+1) ----
        if (tt + 1 < NTILES) {
            store_tile_h(smem + SM_VH + ((tt + 1) & 1) * 4096, lrow, lq, vp);
        }
        __syncthreads();
    }

    // ---- epilogue: normalize (o1 cols all equal: [0]=row g, [2]=row g+8) ----
    float* Ob = O + ((size_t)b * LQ + (size_t)qblk * BM) * DDIM;
    #pragma unroll
    for (int rb = 0; rb < 2; rb++) {
        const float i0 = 1.0f / o1[rb][0];
        const float i1 = 1.0f / o1[rb][2];
        #pragma unroll
        for (int nb = 0; nb < 8; nb++) {
            int row = r0 + 16 * rb + g;
            int col = 8 * nb + 2 * t4;
            *reinterpret_cast<float2*>(&Ob[(size_t)row * DDIM + col]) =
                make_float2(o[rb][nb][0] * i0, o[rb][nb][1] * i0);
            *reinterpret_cast<float2*>(&Ob[(size_t)(row + 8) * DDIM + col]) =
                make_float2(o[rb][nb][2] * i1, o[rb][nb][3] * i1);
        }
    }
}

extern "C" void kernel_launch(void* const* d_in, const int* in_sizes, int n_in,
                              void* d_out, int out_size)
{
    const float* Q = (const float*)d_in[0];
    const float* K = (const float*)d_in[1];
    const float* V = (const float*)d_in[2];
    float* O = (float*)d_out;

    cudaFuncSetAttribute(fa9, cudaFuncAttributeMaxDynamicSharedMemorySize, SM_TOTAL);
    dim3 grid(LQ / BM, BATCH);
    fa9<<<grid, NT, SM_TOTAL>>>(Q, K, V, O);
}

// round 16
// speedup vs baseline: 1.3870x; 1.3720x over previous
#include <cuda_runtime.h>
#include <cuda_fp16.h>
#include <cstdint>

#define BATCH 32
#define LQ    2048
#define SK    2048
#define EDIM  64
#define DDIM  64

#define BM 128
#define BN 32
#define NT 128
#define NTILES (SK / BN)

#define QSCALE 0.18033688011112042f   // (1/sqrt(64)) * log2(e)
#define ONES_H2 0x3C003C00u           // half2(1.0, 1.0)

// ---- shared memory (bytes) ----
#define SM_KH  0          // double buf fp16 K image 32x128B -> 4096 B each
#define SM_VH  8192       // double buf fp16 V image 32x128B -> 4096 B each
#define SM_TOTAL 16384

// ---- fp16 scratch (swizzled smem-image layout), 8 MB each ----
__device__ __half KS_h[(size_t)BATCH * SK * EDIM];
__device__ __half VS_h[(size_t)BATCH * SK * DDIM];

__device__ __forceinline__ uint32_t smem_u32(const void* p) {
    uint32_t a;
    asm("{ .reg .u64 t; cvta.to.shared.u64 t, %1; cvt.u32.u64 %0, t; }" : "=r"(a) : "l"(p));
    return a;
}
__device__ __forceinline__ float ex2(float x) {
    float r;
    asm("ex2.approx.ftz.f32 %0, %1;" : "=f"(r) : "f"(x));
    return r;
}
__device__ __forceinline__ uint32_t pack_h2(float lo, float hi) {
    __half2 h = __floats2half2_rn(lo, hi);
    return *reinterpret_cast<uint32_t*>(&h);
}
__device__ __forceinline__ void mma16(float c[4], const uint32_t a[4],
                                      uint32_t b0, uint32_t b1) {
    asm volatile(
        "mma.sync.aligned.m16n8k16.row.col.f32.f16.f16.f32 "
        "{%0,%1,%2,%3}, {%4,%5,%6,%7}, {%8,%9}, {%0,%1,%2,%3};"
        : "+f"(c[0]), "+f"(c[1]), "+f"(c[2]), "+f"(c[3])
        : "r"(a[0]), "r"(a[1]), "r"(a[2]), "r"(a[3]), "r"(b0), "r"(b1));
}
__device__ __forceinline__ void ldsm4(uint32_t r[4], uint32_t addr) {
    asm volatile("ldmatrix.sync.aligned.m8n8.x4.shared.b16 {%0,%1,%2,%3}, [%4];"
        : "=r"(r[0]), "=r"(r[1]), "=r"(r[2]), "=r"(r[3]) : "r"(addr));
}
__device__ __forceinline__ void ldsm4t(uint32_t r[4], uint32_t addr) {
    asm volatile("ldmatrix.sync.aligned.m8n8.x4.trans.shared.b16 {%0,%1,%2,%3}, [%4];"
        : "=r"(r[0]), "=r"(r[1]), "=r"(r[2]), "=r"(r[3]) : "r"(addr));
}
__device__ __forceinline__ void cp16(uint32_t smem, const void* g) {
    asm volatile(
        "{ .reg .u64 gp; cvta.to.global.u64 gp, %1;\n\t"
        "cp.async.cg.shared.global [%0], [gp], 16; }"
        :: "r"(smem), "l"(g) : "memory");
}
#define CP_COMMIT() asm volatile("cp.async.commit_group;" ::: "memory")
#define CP_WAIT0()  asm volatile("cp.async.wait_group 0;" ::: "memory")

// K fragments for one nb (8 regs)
__device__ __forceinline__ void ld_kfrags(uint32_t w[8], uint32_t kb, int nb) {
    uint32_t a = kb + (uint32_t)(nb * 1024);
    ldsm4(w,     a);
    ldsm4(w + 4, a ^ 64u);
}
// V fragments for one ks (16 regs)
__device__ __forceinline__ void ld_vfrags(uint32_t v[16], uint32_t vb, int ks) {
    uint32_t a = vb + (uint32_t)(ks * 2048);
    ldsm4t(v,      a);
    ldsm4t(v + 4,  a ^ 32u);
    ldsm4t(v + 8,  a ^ 64u);
    ldsm4t(v + 12, a ^ 96u);
}

// ---- pre-pass: fp32 K/V -> fp16 scratch in swizzled image layout ----
// one thread = one 16B chunk (8 halves) of K and of V
__global__ __launch_bounds__(256)
void cvt_half(const float* __restrict__ K, const float* __restrict__ V)
{
    size_t idx = (size_t)blockIdx.x * 256 + threadIdx.x;  // 0 .. 32*2048*8-1
    size_t row = idx >> 3;          // global key row (b*2048 + key)
    int    ch  = (int)(idx & 7);
    int    r7  = (int)(row & 7);
    size_t dst = row * 128 + (size_t)((ch ^ r7) << 4);    // byte offset

    const float4* ks = reinterpret_cast<const float4*>(K + row * 64 + ch * 8);
    float4 a = ks[0], b = ks[1];
    uint4 h = make_uint4(pack_h2(a.x, a.y), pack_h2(a.z, a.w),
                         pack_h2(b.x, b.y), pack_h2(b.z, b.w));
    *reinterpret_cast<uint4*>(reinterpret_cast<char*>(KS_h) + dst) = h;

    const float4* vs = reinterpret_cast<const float4*>(V + row * 64 + ch * 8);
    a = vs[0]; b = vs[1];
    h = make_uint4(pack_h2(a.x, a.y), pack_h2(a.z, a.w),
                   pack_h2(b.x, b.y), pack_h2(b.z, b.w));
    *reinterpret_cast<uint4*>(reinterpret_cast<char*>(VS_h) + dst) = h;
}

__global__ __launch_bounds__(NT, 2)
void fa10(const float* __restrict__ Q, float* __restrict__ O)
{
    extern __shared__ char smem[];
    const uint32_t sb = smem_u32(smem);

    const int tid  = threadIdx.x;
    const int lane = tid & 31;
    const int warp = tid >> 5;
    const int g    = lane >> 2;
    const int t4   = lane & 3;
    const int r0   = warp << 5;            // 32 query rows per warp

    const int b    = blockIdx.y;
    const int qblk = blockIdx.x;
    const float* Qb = Q + ((size_t)b * LQ + (size_t)qblk * BM) * EDIM;
    const char* kscr = reinterpret_cast<const char*>(KS_h) + (size_t)b * SK * 128;
    const char* vscr = reinterpret_cast<const char*>(VS_h) + (size_t)b * SK * 128;

    // ldmatrix lane-constant address parts (layouts verified R9/R13)
    const int l7 = lane & 7;
    const int lm = lane >> 3;
    const uint32_t kla = (uint32_t)(l7 * 128 + ((lm ^ l7) << 4));
    const uint32_t vla = (uint32_t)(((lm & 1) * 8 + l7) * 128 + ((((lm >> 1) ^ l7)) << 4));

    // ---- prologue: async-copy tile 0 into buf 0 ----
    {
        uint32_t kd = sb + SM_KH + (uint32_t)(tid * 32);
        uint32_t vd = sb + SM_VH + (uint32_t)(tid * 32);
        cp16(kd,      kscr + tid * 32);
        cp16(kd + 16, kscr + tid * 32 + 16);
        cp16(vd,      vscr + tid * 32);
        cp16(vd + 16, vscr + tid * 32 + 16);
        CP_COMMIT();
    }

    // ---- Q -> fp16 A-fragments in 32 persistent registers ----
    uint32_t aq[2][4][4];
    #pragma unroll
    for (int rb = 0; rb < 2; rb++) {
        const float* q0 = Qb + (size_t)(r0 + 16 * rb + g) * EDIM;
        const float* q1 = q0 + 8 * EDIM;
        #pragma unroll
        for (int kk = 0; kk < 4; kk++) {
            int c = 16 * kk + 2 * t4;
            aq[rb][kk][0] = pack_h2(q0[c    ] * QSCALE, q0[c + 1] * QSCALE);
            aq[rb][kk][1] = pack_h2(q1[c    ] * QSCALE, q1[c + 1] * QSCALE);
            aq[rb][kk][2] = pack_h2(q0[c + 8] * QSCALE, q0[c + 9] * QSCALE);
            aq[rb][kk][3] = pack_h2(q1[c + 8] * QSCALE, q1[c + 9] * QSCALE);
        }
    }
    CP_WAIT0();
    __syncthreads();

    float o[2][8][4];
    #pragma unroll
    for (int rb = 0; rb < 2; rb++)
        #pragma unroll
        for (int nb = 0; nb < 8; nb++)
            #pragma unroll
            for (int i = 0; i < 4; i++) o[rb][nb][i] = 0.0f;
    float o1[2][4];                        // ones-column row sums
    #pragma unroll
    for (int rb = 0; rb < 2; rb++)
        #pragma unroll
        for (int i = 0; i < 4; i++) o1[rb][i] = 0.0f;

    for (int tt = 0; tt < NTILES; tt++) {
        const uint32_t kb = sb + SM_KH + (uint32_t)((tt & 1) * 4096) + kla;
        const uint32_t vb = sb + SM_VH + (uint32_t)((tt & 1) * 4096) + vla;

        // ---- async-copy tile tt+1 into alternate buffers ----
        if (tt + 1 < NTILES) {
            const char* ks = kscr + (size_t)(tt + 1) * 4096;
            const char* vs = vscr + (size_t)(tt + 1) * 4096;
            uint32_t kd = sb + SM_KH + (uint32_t)(((tt + 1) & 1) * 4096 + tid * 32);
            uint32_t vd = sb + SM_VH + (uint32_t)(((tt + 1) & 1) * 4096 + tid * 32);
            cp16(kd,      ks + tid * 32);
            cp16(kd + 16, ks + tid * 32 + 16);
            cp16(vd,      vs + tid * 32);
            cp16(vd + 16, vs + tid * 32 + 16);
            CP_COMMIT();
        }

        // ---- MMA1 fused with softmax, software-pipelined K LDSM ----
        uint32_t ph[2][4][2];
        uint32_t wf[2][8];
        ld_kfrags(wf[0], kb, 0);
        #pragma unroll
        for (int nb = 0; nb < 4; nb++) {
            const uint32_t* w = wf[nb & 1];
            if (nb < 3) ld_kfrags(wf[(nb + 1) & 1], kb, nb + 1);
            #pragma unroll
            for (int rb = 0; rb < 2; rb++) {
                float sL[4] = {0, 0, 0, 0}, sH[4] = {0, 0, 0, 0};
                mma16(sL, aq[rb][0], w[0], w[1]);
                mma16(sL, aq[rb][1], w[2], w[3]);
                mma16(sH, aq[rb][2], w[4], w[5]);
                mma16(sH, aq[rb][3], w[6], w[7]);
                float p0 = ex2(sL[0] + sH[0]);
                float p1 = ex2(sL[1] + sH[1]);
                float p2 = ex2(sL[2] + sH[2]);
                float p3 = ex2(sL[3] + sH[3]);
                ph[rb][nb][0] = pack_h2(p0, p1);
                ph[rb][nb][1] = pack_h2(p2, p3);
            }
        }

        // ---- MMA2: O += P V, software-pipelined V LDSM; ones-MMA row sums ----
        uint32_t vf[2][16];
        ld_vfrags(vf[0], vb, 0);
        #pragma unroll
        for (int ks = 0; ks < 2; ks++) {
            const uint32_t* v = vf[ks & 1];
            if (ks == 0) ld_vfrags(vf[1], vb, 1);
            uint32_t a0[4] = {ph[0][2 * ks][0], ph[0][2 * ks][1],
                              ph[0][2 * ks + 1][0], ph[0][2 * ks + 1][1]};
            uint32_t a1[4] = {ph[1][2 * ks][0], ph[1][2 * ks][1],
                              ph[1][2 * ks + 1][0], ph[1][2 * ks + 1][1]};
            #pragma unroll
            for (int nbp = 0; nbp < 4; nbp++) {
                mma16(o[0][2 * nbp    ], a0, v[4 * nbp + 0], v[4 * nbp + 1]);
                mma16(o[0][2 * nbp + 1], a0, v[4 * nbp + 2], v[4 * nbp + 3]);
                mma16(o[1][2 * nbp    ], a1, v[4 * nbp + 0], v[4 * nbp + 1]);
                mma16(o[1][2 * nbp + 1], a1, v[4 * nbp + 2], v[4 * nbp + 3]);
            }
            mma16(o1[0], a0, ONES_H2, ONES_H2);
            mma16(o1[1], a1, ONES_H2, ONES_H2);
        }

        CP_WAIT0();
        __syncthreads();
    }

    // ---- epilogue: normalize (o1 cols equal: [0]=row g, [2]=row g+8) ----
    float* Ob = O + ((size_t)b * LQ + (size_t)qblk * BM) * DDIM;
    #pragma unroll
    for (int rb = 0; rb < 2; rb++) {
        const float i0 = 1.0f / o1[rb][0];
        const float i1 = 1.0f / o1[rb][2];
        #pragma unroll
        for (int nb = 0; nb < 8; nb++) {
            int row = r0 + 16 * rb + g;
            int col = 8 * nb + 2 * t4;
            *reinterpret_cast<float2*>(&Ob[(size_t)row * DDIM + col]) =
                make_float2(o[rb][nb][0] * i0, o[rb][nb][1] * i0);
            *reinterpret_cast<float2*>(&Ob[(size_t)(row + 8) * DDIM + col]) =
                make_float2(o[rb][nb][2] * i1, o[rb][nb][3] * i1);
        }
    }
}

extern "C" void kernel_launch(void* const* d_in, const int* in_sizes, int n_in,
                              void* d_out, int out_size)
{
    const float* Q = (const float*)d_in[0];
    const float* K = (const float*)d_in[1];
    const float* V = (const float*)d_in[2];
    float* O = (float*)d_out;

    // pre-pass: fp32 -> fp16 swizzled-image scratch (32*2048*8 chunks)
    cvt_half<<<(BATCH * SK * 8) / 256, 256>>>(K, V);

    cudaFuncSetAttribute(fa10, cudaFuncAttributeMaxDynamicSharedMemorySize, SM_TOTAL);
    dim3 grid(LQ / BM, BATCH);
    fa10<<<grid, NT, SM_TOTAL>>>(Q, O);
}